// round 1
// baseline (speedup 1.0000x reference)
#include <cuda_runtime.h>

#define NV 20000
#define EE 320000
#define DD 128
#define HD 512
#define LL 3
#define EPS_ 1.1920929e-07f

// ---------------- scratch (static device memory; no allocations) ----------------
__device__ float g_x[NV * DD];            // current node features (10.24 MB)
__device__ float g_xp[(size_t)NV * HD];   // x @ W_gat  (40.96 MB)
__device__ float g_h1[NV * DD];
__device__ float g_tmp[NV * DD];
__device__ float g_as[NV * 4];
__device__ float g_ad[NV * 4];
__device__ int   g_rowptr[NV + 1];
__device__ int   g_deg[NV];
__device__ int   g_cursor[NV];
__device__ int   g_col[EE + NV];
__device__ int   g_is64;

// ---------------- edge-index dtype handling ----------------
__device__ __forceinline__ int edge_at(const void* ei, long long idx) {
    return g_is64 ? (int)((const long long*)ei)[idx] : ((const int*)ei)[idx];
}

__global__ void k_detect(const unsigned* w) {
    // If int64 little-endian with values in [0, 2^31), every odd 32-bit word is 0.
    __shared__ unsigned acc;
    if (threadIdx.x == 0) acc = 0u;
    __syncthreads();
    unsigned v = 0;
    for (int i = threadIdx.x; i < 2048; i += 256) v |= w[2 * i + 1];
    if (v) atomicOr(&acc, 1u);
    __syncthreads();
    if (threadIdx.x == 0) g_is64 = (acc == 0u) ? 1 : 0;
}

// ---------------- CSR build ----------------
__global__ void k_initdeg() {
    int n = blockIdx.x * 256 + threadIdx.x;
    if (n < NV) g_deg[n] = 1;  // self loop
}
__global__ void k_count(const void* ei) {
    int e = blockIdx.x * 256 + threadIdx.x;
    if (e < EE) {
        int d = edge_at(ei, (long long)EE + e);
        atomicAdd(&g_deg[d], 1);
    }
}
__global__ void k_scan() {  // single block, 1024 threads, chunked Hillis-Steele
    __shared__ int sh[1024];
    __shared__ int carry;
    int t = threadIdx.x;
    if (t == 0) { carry = 0; g_rowptr[0] = 0; }
    __syncthreads();
    for (int base = 0; base < NV; base += 1024) {
        int i = base + t;
        sh[t] = (i < NV) ? g_deg[i] : 0;
        __syncthreads();
        for (int o = 1; o < 1024; o <<= 1) {
            int add = (t >= o) ? sh[t - o] : 0;
            __syncthreads();
            sh[t] += add;
            __syncthreads();
        }
        if (i < NV) g_rowptr[i + 1] = carry + sh[t];
        __syncthreads();
        if (t == 0) carry += sh[1023];
        __syncthreads();
    }
}
__global__ void k_fill() {
    int n = blockIdx.x * 256 + threadIdx.x;
    if (n < NV) {
        int r = g_rowptr[n];
        g_col[r] = n;          // self loop at slot 0
        g_cursor[n] = r + 1;
    }
}
__global__ void k_scatter(const void* ei) {
    int e = blockIdx.x * 256 + threadIdx.x;
    if (e < EE) {
        int s = edge_at(ei, e);
        int d = edge_at(ei, (long long)EE + e);
        int idx = atomicAdd(&g_cursor[d], 1);
        g_col[idx] = s;
    }
}

// ---------------- copies ----------------
__global__ void k_loadx(const float4* __restrict__ x) {
    int i = blockIdx.x * 256 + threadIdx.x;
    if (i < NV * DD / 4) ((float4*)g_x)[i] = x[i];
}
__global__ void k_storeout(float4* __restrict__ out) {
    int i = blockIdx.x * 256 + threadIdx.x;
    if (i < NV * DD / 4) out[i] = ((const float4*)g_x)[i];
}

// ---------------- SGEMM: C[M,Ncols] = A[M,128] * B[128,Ncols] (+bias)(+relu) ----------------
// BM=BN=128, BK=8, 256 threads, 8x8 per thread (split 4+4 to reduce LDS conflicts)
__global__ __launch_bounds__(256) void sgemm128(
    const float* __restrict__ A, const float* __restrict__ B,
    const float* __restrict__ bias, float* __restrict__ C,
    int M, int Ncols, int relu)
{
    __shared__ float As[8][128];
    __shared__ float Bs[8][128];
    int bm = blockIdx.y * 128;
    int bn = blockIdx.x * 128;
    int t = threadIdx.x;
    int tx = t & 15, ty = t >> 4;

    float acc[8][8];
#pragma unroll
    for (int i = 0; i < 8; i++)
#pragma unroll
        for (int j = 0; j < 8; j++) acc[i][j] = 0.f;

    int arow = t >> 1;         // 0..127
    int akg = (t & 1) * 4;     // 0 or 4
    int brow = t >> 5;         // 0..7
    int bcol = (t & 31) * 4;   // 0..124
    bool aval = (bm + arow) < M;
    const float* Aptr = A + (size_t)(bm + arow) * 128 + akg;

    for (int k0 = 0; k0 < 128; k0 += 8) {
        float4 av = aval ? *(const float4*)(Aptr + k0) : make_float4(0.f, 0.f, 0.f, 0.f);
        As[akg + 0][arow] = av.x;
        As[akg + 1][arow] = av.y;
        As[akg + 2][arow] = av.z;
        As[akg + 3][arow] = av.w;
        float4 bv = *(const float4*)&B[(size_t)(k0 + brow) * Ncols + bn + bcol];
        *(float4*)&Bs[brow][bcol] = bv;
        __syncthreads();
#pragma unroll
        for (int kk = 0; kk < 8; kk++) {
            float a[8], b[8];
            *(float4*)&a[0] = *(const float4*)&As[kk][ty * 4];
            *(float4*)&a[4] = *(const float4*)&As[kk][64 + ty * 4];
            *(float4*)&b[0] = *(const float4*)&Bs[kk][tx * 4];
            *(float4*)&b[4] = *(const float4*)&Bs[kk][64 + tx * 4];
#pragma unroll
            for (int i = 0; i < 8; i++)
#pragma unroll
                for (int j = 0; j < 8; j++) acc[i][j] += a[i] * b[j];
        }
        __syncthreads();
    }

    // epilogue: rows {bm+ty*4+i, bm+64+ty*4+i}, cols {bn+tx*4.., bn+64+tx*4..}
#pragma unroll
    for (int half = 0; half < 2; half++) {
#pragma unroll
        for (int i = 0; i < 4; i++) {
            int r = bm + half * 64 + ty * 4 + i;
            if (r >= M) continue;
            int ai = half * 4 + i;
#pragma unroll
            for (int ch = 0; ch < 2; ch++) {
                int c = bn + ch * 64 + tx * 4;
                float4 v;
                v.x = acc[ai][ch * 4 + 0];
                v.y = acc[ai][ch * 4 + 1];
                v.z = acc[ai][ch * 4 + 2];
                v.w = acc[ai][ch * 4 + 3];
                if (bias) {
                    const float4 bb = *(const float4*)&bias[c];
                    v.x += bb.x; v.y += bb.y; v.z += bb.z; v.w += bb.w;
                }
                if (relu) {
                    v.x = fmaxf(v.x, 0.f); v.y = fmaxf(v.y, 0.f);
                    v.z = fmaxf(v.z, 0.f); v.w = fmaxf(v.w, 0.f);
                }
                *(float4*)&C[(size_t)r * Ncols + c] = v;
            }
        }
    }
}

// ---------------- attention dot products: a_s/a_d per (node, head) ----------------
__global__ __launch_bounds__(128) void k_dots(const float* __restrict__ att_s,
                                              const float* __restrict__ att_d) {
    int warp = threadIdx.x >> 5, lane = threadIdx.x & 31;
    int n = blockIdx.x * 4 + warp;
    if (n >= NV) return;
    const float* xpr = g_xp + (size_t)n * HD;
#pragma unroll
    for (int h = 0; h < 4; h++) {
        float4 xv = *(const float4*)&xpr[h * 128 + lane * 4];
        float4 as = *(const float4*)&att_s[h * 128 + lane * 4];
        float4 ad = *(const float4*)&att_d[h * 128 + lane * 4];
        float ps = xv.x * as.x + xv.y * as.y + xv.z * as.z + xv.w * as.w;
        float pd = xv.x * ad.x + xv.y * ad.y + xv.z * ad.z + xv.w * ad.w;
#pragma unroll
        for (int o = 16; o; o >>= 1) {
            ps += __shfl_xor_sync(0xffffffffu, ps, o);
            pd += __shfl_xor_sync(0xffffffffu, pd, o);
        }
        if (lane == 0) {
            g_as[n * 4 + h] = ps;
            g_ad[n * 4 + h] = pd;
        }
    }
}

__device__ __forceinline__ float lrelu(float x) { return x > 0.f ? x : 0.2f * x; }

__device__ __forceinline__ float blk_max4(float v, float* sh) {
#pragma unroll
    for (int o = 16; o; o >>= 1) v = fmaxf(v, __shfl_xor_sync(0xffffffffu, v, o));
    int w = threadIdx.x >> 5;
    if ((threadIdx.x & 31) == 0) sh[w] = v;
    __syncthreads();
    float r = fmaxf(fmaxf(sh[0], sh[1]), fmaxf(sh[2], sh[3]));
    __syncthreads();
    return r;
}
__device__ __forceinline__ float blk_sum4(float v, float* sh) {
#pragma unroll
    for (int o = 16; o; o >>= 1) v += __shfl_xor_sync(0xffffffffu, v, o);
    int w = threadIdx.x >> 5;
    if ((threadIdx.x & 31) == 0) sh[w] = v;
    __syncthreads();
    float r = sh[0] + sh[1] + sh[2] + sh[3];
    __syncthreads();
    return r;
}

// ---------------- fused GAT aggregation: softmax + weighted gather + head mean
//                  + bias + residual + RMSNorm. One block (128 threads) per dst node.
__global__ __launch_bounds__(128) void k_agg(const float* __restrict__ bias,
                                             const float* __restrict__ nw) {
    int n = blockIdx.x, t = threadIdx.x;
    int start = g_rowptr[n];
    int deg = g_rowptr[n + 1] - start;

    __shared__ float shr[4];
    __shared__ float sh_alpha[128][4];
    __shared__ int sh_src[128];
    __shared__ float shred[128];

    float4 adv = *(const float4*)&g_ad[n * 4];

    // pass 1: segment max per head
    float m0 = -1e30f, m1 = -1e30f, m2 = -1e30f, m3 = -1e30f;
    for (int j = t; j < deg; j += 128) {
        int s = g_col[start + j];
        float4 asv = *(const float4*)&g_as[s * 4];
        m0 = fmaxf(m0, lrelu(asv.x + adv.x));
        m1 = fmaxf(m1, lrelu(asv.y + adv.y));
        m2 = fmaxf(m2, lrelu(asv.z + adv.z));
        m3 = fmaxf(m3, lrelu(asv.w + adv.w));
    }
    m0 = blk_max4(m0, shr); m1 = blk_max4(m1, shr);
    m2 = blk_max4(m2, shr); m3 = blk_max4(m3, shr);

    // pass 2: denom per head
    float s0 = 0.f, s1 = 0.f, s2 = 0.f, s3 = 0.f;
    for (int j = t; j < deg; j += 128) {
        int s = g_col[start + j];
        float4 asv = *(const float4*)&g_as[s * 4];
        s0 += __expf(lrelu(asv.x + adv.x) - m0);
        s1 += __expf(lrelu(asv.y + adv.y) - m1);
        s2 += __expf(lrelu(asv.z + adv.z) - m2);
        s3 += __expf(lrelu(asv.w + adv.w) - m3);
    }
    s0 = blk_sum4(s0, shr); s1 = blk_sum4(s1, shr);
    s2 = blk_sum4(s2, shr); s3 = blk_sum4(s3, shr);
    float i0 = 1.f / s0, i1 = 1.f / s1, i2 = 1.f / s2, i3 = 1.f / s3;

    // pass 3: weighted gather accumulate (thread t owns output dim t)
    float acc = 0.f;
    for (int c0 = 0; c0 < deg; c0 += 128) {
        int j = c0 + t;
        if (j < deg) {
            int s = g_col[start + j];
            sh_src[t] = s;
            float4 asv = *(const float4*)&g_as[s * 4];
            sh_alpha[t][0] = __expf(lrelu(asv.x + adv.x) - m0) * i0;
            sh_alpha[t][1] = __expf(lrelu(asv.y + adv.y) - m1) * i1;
            sh_alpha[t][2] = __expf(lrelu(asv.z + adv.z) - m2) * i2;
            sh_alpha[t][3] = __expf(lrelu(asv.w + adv.w) - m3) * i3;
        }
        __syncthreads();
        int cnt = min(128, deg - c0);
        for (int jj = 0; jj < cnt; jj++) {
            const float* xr = g_xp + (size_t)sh_src[jj] * HD + t;
            acc += sh_alpha[jj][0] * xr[0]   + sh_alpha[jj][1] * xr[128]
                 + sh_alpha[jj][2] * xr[256] + sh_alpha[jj][3] * xr[384];
        }
        __syncthreads();
    }

    // head mean + bias + residual + RMSNorm
    float v = g_x[n * DD + t] + 0.25f * acc + bias[t];
    shred[t] = v * v;
    __syncthreads();
#pragma unroll
    for (int o = 64; o; o >>= 1) {
        if (t < o) shred[t] += shred[t + o];
        __syncthreads();
    }
    float r = rsqrtf(shred[0] * (1.0f / DD) + EPS_);
    g_x[n * DD + t] = v * r * nw[t];
}

// ---------------- residual + RMSNorm after FFN ----------------
__global__ __launch_bounds__(128) void k_resnorm(const float* __restrict__ nw) {
    int n = blockIdx.x, t = threadIdx.x;
    __shared__ float shred[128];
    float v = g_x[n * DD + t] + g_tmp[n * DD + t];
    shred[t] = v * v;
    __syncthreads();
#pragma unroll
    for (int o = 64; o; o >>= 1) {
        if (t < o) shred[t] += shred[t + o];
        __syncthreads();
    }
    float r = rsqrtf(shred[0] * (1.0f / DD) + EPS_);
    g_x[n * DD + t] = v * r * nw[t];
}

// ---------------- host ----------------
extern "C" void kernel_launch(void* const* d_in, const int* in_sizes, int n_in,
                              void* d_out, int out_size) {
    const float* x        = (const float*)d_in[0];
    const float* W_gat    = (const float*)d_in[1];
    const float* att_src  = (const float*)d_in[2];
    const float* att_dst  = (const float*)d_in[3];
    const float* bias_gat = (const float*)d_in[4];
    const float* W1       = (const float*)d_in[5];
    const float* b1       = (const float*)d_in[6];
    const float* W2       = (const float*)d_in[7];
    const float* b2       = (const float*)d_in[8];
    const float* n1w      = (const float*)d_in[9];
    const float* n2w      = (const float*)d_in[10];
    const void*  ei       = d_in[11];

    float *xbuf, *xpbuf, *h1buf, *tmpbuf;
    cudaGetSymbolAddress((void**)&xbuf, g_x);
    cudaGetSymbolAddress((void**)&xpbuf, g_xp);
    cudaGetSymbolAddress((void**)&h1buf, g_h1);
    cudaGetSymbolAddress((void**)&tmpbuf, g_tmp);

    // CSR build (same every call; deterministic edge sets per node)
    k_detect<<<1, 256>>>((const unsigned*)ei);
    k_initdeg<<<(NV + 255) / 256, 256>>>();
    k_count<<<(EE + 255) / 256, 256>>>(ei);
    k_scan<<<1, 1024>>>();
    k_fill<<<(NV + 255) / 256, 256>>>();
    k_scatter<<<(EE + 255) / 256, 256>>>(ei);

    k_loadx<<<(NV * DD / 4 + 255) / 256, 256>>>((const float4*)x);

    int MT = (NV + 127) / 128;  // 157 row tiles
    for (int i = 0; i < LL; i++) {
        sgemm128<<<dim3(HD / 128, MT), 256>>>(xbuf, W_gat + (size_t)i * DD * HD,
                                              nullptr, xpbuf, NV, HD, 0);
        k_dots<<<(NV + 3) / 4, 128>>>(att_src + i * HD, att_dst + i * HD);
        k_agg<<<NV, 128>>>(bias_gat + i * DD, n1w + i * DD);
        sgemm128<<<dim3(1, MT), 256>>>(xbuf, W1 + (size_t)i * DD * DD,
                                       b1 + i * DD, h1buf, NV, DD, 1);
        sgemm128<<<dim3(1, MT), 256>>>(h1buf, W2 + (size_t)i * DD * DD,
                                       b2 + i * DD, tmpbuf, NV, DD, 0);
        k_resnorm<<<NV, 128>>>(n2w + i * DD);
    }

    k_storeout<<<(NV * DD / 4 + 255) / 256, 256>>>((float4*)d_out);
}

// round 2
// speedup vs baseline: 1.2505x; 1.2505x over previous
#include <cuda_runtime.h>
#include <mma.h>
using namespace nvcuda;

#define NV 20000
#define EE 320000
#define DD 128
#define HD 512
#define LL 3
#define MTILES 157
#define NV2 (MTILES * 128)   /* 20096, padded row count */
#define EPS_ 1.1920929e-07f

// ---------------- scratch (static device memory; no allocations) ----------------
__device__ float g_x[NV2 * DD];
__device__ float g_xp[(size_t)NV2 * HD];
__device__ float g_h1[NV2 * DD];
__device__ float g_tmp[NV2 * DD];
__device__ float g_as[NV * 4];
__device__ float g_ad[NV * 4];
__device__ int   g_rowptr[NV + 1];
__device__ int   g_deg[NV];
__device__ int   g_cursor[NV];
__device__ int   g_col[EE + NV];
__device__ int   g_is64;

// ---------------- edge-index dtype handling ----------------
__device__ __forceinline__ int edge_at(const void* ei, long long idx) {
    return g_is64 ? (int)((const long long*)ei)[idx] : ((const int*)ei)[idx];
}

__global__ void k_detect(const unsigned* w) {
    __shared__ unsigned acc;
    if (threadIdx.x == 0) acc = 0u;
    __syncthreads();
    unsigned v = 0;
    for (int i = threadIdx.x; i < 2048; i += 256) v |= w[2 * i + 1];
    if (v) atomicOr(&acc, 1u);
    __syncthreads();
    if (threadIdx.x == 0) g_is64 = (acc == 0u) ? 1 : 0;
}

// ---------------- CSR build ----------------
__global__ void k_initdeg() {
    int n = blockIdx.x * 256 + threadIdx.x;
    if (n < NV) g_deg[n] = 1;  // self loop
}
__global__ void k_count(const void* ei) {
    int e = blockIdx.x * 256 + threadIdx.x;
    if (e < EE) {
        int d = edge_at(ei, (long long)EE + e);
        atomicAdd(&g_deg[d], 1);
    }
}
// thread-coarsened scan: 1024 threads x 20 elements, warp shfl scans
__global__ __launch_bounds__(1024) void k_scan() {
    const int PER = 20;  // 1024*20 = 20480 >= NV
    __shared__ int wsum[32];
    int t = threadIdx.x;
    int lane = t & 31, w = t >> 5;
    int v[PER];
    int base = t * PER;
    int run = 0;
#pragma unroll
    for (int i = 0; i < PER; i++) {
        int idx = base + i;
        int d = (idx < NV) ? g_deg[idx] : 0;
        run += d;
        v[i] = run;  // thread-local inclusive
    }
    int tot = run;
    int sc = tot;  // warp inclusive scan of per-thread totals
#pragma unroll
    for (int o = 1; o < 32; o <<= 1) {
        int u = __shfl_up_sync(0xffffffffu, sc, o);
        if (lane >= o) sc += u;
    }
    if (lane == 31) wsum[w] = sc;
    __syncthreads();
    if (w == 0) {
        int s = wsum[lane];
#pragma unroll
        for (int o = 1; o < 32; o <<= 1) {
            int u = __shfl_up_sync(0xffffffffu, s, o);
            if (lane >= o) s += u;
        }
        wsum[lane] = s;
    }
    __syncthreads();
    int warpoff = (w > 0) ? wsum[w - 1] : 0;
    int throff = warpoff + sc - tot;  // exclusive prefix for this thread
    if (t == 0) g_rowptr[0] = 0;
#pragma unroll
    for (int i = 0; i < PER; i++) {
        int idx = base + i;
        if (idx < NV) g_rowptr[idx + 1] = throff + v[i];
    }
}
__global__ void k_fill() {
    int n = blockIdx.x * 256 + threadIdx.x;
    if (n < NV) {
        int r = g_rowptr[n];
        g_col[r] = n;  // self loop at slot 0
        g_cursor[n] = r + 1;
    }
}
__global__ void k_scatter(const void* ei) {
    int e = blockIdx.x * 256 + threadIdx.x;
    if (e < EE) {
        int s = edge_at(ei, e);
        int d = edge_at(ei, (long long)EE + e);
        int idx = atomicAdd(&g_cursor[d], 1);
        g_col[idx] = s;
    }
}

// ---------------- copies ----------------
__global__ void k_loadx(const float4* __restrict__ x) {
    int i = blockIdx.x * 256 + threadIdx.x;
    if (i < NV * DD / 4) ((float4*)g_x)[i] = x[i];
}
__global__ void k_storeout(float4* __restrict__ out) {
    int i = blockIdx.x * 256 + threadIdx.x;
    if (i < NV * DD / 4) out[i] = ((const float4*)g_x)[i];
}

// ---------------- tf32 tensor-core GEMM ----------------
// C[0:NV2, Ncols] = A[0:NV2,128] * B[128,Ncols] (+bias)(+relu)
// Block tile 128x128, 8 warps (2 row-groups x 4 col-groups), wmma m16n16k8 tf32.
// All row dims padded to NV2 -> no M guards anywhere.
__device__ __forceinline__ float to_tf32(float x) {
    float r;
    asm("cvt.rna.tf32.f32 %0, %1;" : "=f"(r) : "f"(x));
    return r;
}

__global__ __launch_bounds__(256) void gemm_tf32(
    const float* __restrict__ A, const float* __restrict__ B,
    const float* __restrict__ bias, float* __restrict__ C,
    int Ncols, int relu)
{
    __shared__ float As[128][20];    // 128 x 16, pad->20
    __shared__ float Bs[16][132];    // 16 x 128, pad->132
    __shared__ float Brep[16][132];  // bias replicated over 16 rows

    int bm = blockIdx.y * 128, bn = blockIdx.x * 128;
    int t = threadIdx.x;
    int warp = t >> 5;
    int wr = warp & 1;    // row group: 64 rows
    int wc = warp >> 1;   // col group: 32 cols

    // bias replica (zeros if no bias) -> accumulator init
    for (int i = t; i < 16 * 128; i += 256) {
        int r = i >> 7, c = i & 127;
        Brep[r][c] = bias ? bias[bn + c] : 0.f;
    }
    __syncthreads();

    wmma::fragment<wmma::accumulator, 16, 16, 8, float> acc[4][2];
#pragma unroll
    for (int fr = 0; fr < 4; fr++)
#pragma unroll
        for (int fc = 0; fc < 2; fc++)
            wmma::load_matrix_sync(acc[fr][fc], &Brep[0][wc * 32 + fc * 16], 132,
                                   wmma::mem_row_major);

    const float* Aptr = A + (size_t)bm * 128;

    for (int k0 = 0; k0 < 128; k0 += 16) {
        // load A tile 128x16 (2 float4 per thread)
#pragma unroll
        for (int i = 0; i < 2; i++) {
            int idx = t + i * 256;            // 0..511
            int r = idx >> 2, c4 = (idx & 3) * 4;
            float4 v = *(const float4*)&Aptr[(size_t)r * 128 + k0 + c4];
            As[r][c4 + 0] = to_tf32(v.x);
            As[r][c4 + 1] = to_tf32(v.y);
            As[r][c4 + 2] = to_tf32(v.z);
            As[r][c4 + 3] = to_tf32(v.w);
        }
        // load B tile 16x128 (2 float4 per thread)
#pragma unroll
        for (int i = 0; i < 2; i++) {
            int idx = t + i * 256;            // 0..511
            int r = idx >> 5, c4 = (idx & 31) * 4;
            float4 v = *(const float4*)&B[(size_t)(k0 + r) * Ncols + bn + c4];
            Bs[r][c4 + 0] = to_tf32(v.x);
            Bs[r][c4 + 1] = to_tf32(v.y);
            Bs[r][c4 + 2] = to_tf32(v.z);
            Bs[r][c4 + 3] = to_tf32(v.w);
        }
        __syncthreads();
#pragma unroll
        for (int ks = 0; ks < 2; ks++) {
            wmma::fragment<wmma::matrix_a, 16, 16, 8, wmma::precision::tf32,
                           wmma::row_major> af[4];
            wmma::fragment<wmma::matrix_b, 16, 16, 8, wmma::precision::tf32,
                           wmma::row_major> bf[2];
#pragma unroll
            for (int fr = 0; fr < 4; fr++)
                wmma::load_matrix_sync(af[fr], &As[wr * 64 + fr * 16][ks * 8], 20);
#pragma unroll
            for (int fc = 0; fc < 2; fc++)
                wmma::load_matrix_sync(bf[fc], &Bs[ks * 8][wc * 32 + fc * 16], 132);
#pragma unroll
            for (int fr = 0; fr < 4; fr++)
#pragma unroll
                for (int fc = 0; fc < 2; fc++)
                    wmma::mma_sync(acc[fr][fc], af[fr], bf[fc], acc[fr][fc]);
        }
        __syncthreads();
    }

#pragma unroll
    for (int fr = 0; fr < 4; fr++)
#pragma unroll
        for (int fc = 0; fc < 2; fc++) {
            if (relu) {
#pragma unroll
                for (int i = 0; i < acc[fr][fc].num_elements; i++)
                    acc[fr][fc].x[i] = fmaxf(acc[fr][fc].x[i], 0.f);
            }
            wmma::store_matrix_sync(
                &C[(size_t)(bm + wr * 64 + fr * 16) * Ncols + bn + wc * 32 + fc * 16],
                acc[fr][fc], Ncols, wmma::mem_row_major);
        }
}

// ---------------- attention dot products ----------------
__global__ __launch_bounds__(128) void k_dots(const float* __restrict__ att_s,
                                              const float* __restrict__ att_d) {
    int warp = threadIdx.x >> 5, lane = threadIdx.x & 31;
    int n = blockIdx.x * 4 + warp;
    if (n >= NV) return;
    const float* xpr = g_xp + (size_t)n * HD;
#pragma unroll
    for (int h = 0; h < 4; h++) {
        float4 xv = *(const float4*)&xpr[h * 128 + lane * 4];
        float4 as = *(const float4*)&att_s[h * 128 + lane * 4];
        float4 ad = *(const float4*)&att_d[h * 128 + lane * 4];
        float ps = xv.x * as.x + xv.y * as.y + xv.z * as.z + xv.w * as.w;
        float pd = xv.x * ad.x + xv.y * ad.y + xv.z * ad.z + xv.w * ad.w;
#pragma unroll
        for (int o = 16; o; o >>= 1) {
            ps += __shfl_xor_sync(0xffffffffu, ps, o);
            pd += __shfl_xor_sync(0xffffffffu, pd, o);
        }
        if (lane == 0) {
            g_as[n * 4 + h] = ps;
            g_ad[n * 4 + h] = pd;
        }
    }
}

__device__ __forceinline__ float lrelu(float x) { return x > 0.f ? x : 0.2f * x; }

__device__ __forceinline__ float blk_max4(float v, float* sh) {
#pragma unroll
    for (int o = 16; o; o >>= 1) v = fmaxf(v, __shfl_xor_sync(0xffffffffu, v, o));
    int w = threadIdx.x >> 5;
    if ((threadIdx.x & 31) == 0) sh[w] = v;
    __syncthreads();
    float r = fmaxf(fmaxf(sh[0], sh[1]), fmaxf(sh[2], sh[3]));
    __syncthreads();
    return r;
}
__device__ __forceinline__ float blk_sum4(float v, float* sh) {
#pragma unroll
    for (int o = 16; o; o >>= 1) v += __shfl_xor_sync(0xffffffffu, v, o);
    int w = threadIdx.x >> 5;
    if ((threadIdx.x & 31) == 0) sh[w] = v;
    __syncthreads();
    float r = sh[0] + sh[1] + sh[2] + sh[3];
    __syncthreads();
    return r;
}

// ---------------- fused GAT aggregation (softmax + gather + mean + bias
//                  + residual + RMSNorm). One 128-thread block per dst node.
//                  Gather uses float4: thread = head*32 + quad.
__global__ __launch_bounds__(128) void k_agg(const float* __restrict__ bias,
                                             const float* __restrict__ nw) {
    int n = blockIdx.x, t = threadIdx.x;
    int start = g_rowptr[n];
    int deg = g_rowptr[n + 1] - start;

    __shared__ float shr[4];
    __shared__ float sh_alpha[128][4];
    __shared__ int sh_src[128];
    __shared__ float xatt[4][128];
    __shared__ float shred[128];

    float4 adv = *(const float4*)&g_ad[n * 4];

    // pass 1: segment max per head
    float m0 = -1e30f, m1 = -1e30f, m2 = -1e30f, m3 = -1e30f;
    for (int j = t; j < deg; j += 128) {
        int s = g_col[start + j];
        float4 asv = *(const float4*)&g_as[s * 4];
        m0 = fmaxf(m0, lrelu(asv.x + adv.x));
        m1 = fmaxf(m1, lrelu(asv.y + adv.y));
        m2 = fmaxf(m2, lrelu(asv.z + adv.z));
        m3 = fmaxf(m3, lrelu(asv.w + adv.w));
    }
    m0 = blk_max4(m0, shr); m1 = blk_max4(m1, shr);
    m2 = blk_max4(m2, shr); m3 = blk_max4(m3, shr);

    // pass 2: denom per head
    float s0 = 0.f, s1 = 0.f, s2 = 0.f, s3 = 0.f;
    for (int j = t; j < deg; j += 128) {
        int s = g_col[start + j];
        float4 asv = *(const float4*)&g_as[s * 4];
        s0 += __expf(lrelu(asv.x + adv.x) - m0);
        s1 += __expf(lrelu(asv.y + adv.y) - m1);
        s2 += __expf(lrelu(asv.z + adv.z) - m2);
        s3 += __expf(lrelu(asv.w + adv.w) - m3);
    }
    s0 = blk_sum4(s0, shr); s1 = blk_sum4(s1, shr);
    s2 = blk_sum4(s2, shr); s3 = blk_sum4(s3, shr);
    float i0 = 1.f / s0, i1 = 1.f / s1, i2 = 1.f / s2, i3 = 1.f / s3;

    // pass 3: weighted gather. thread owns (head h, quad q) -> float4 of dims.
    int h = t >> 5, q = t & 31;
    float4 acc4 = make_float4(0.f, 0.f, 0.f, 0.f);
    for (int c0 = 0; c0 < deg; c0 += 128) {
        int j = c0 + t;
        if (j < deg) {
            int s = g_col[start + j];
            sh_src[t] = s;
            float4 asv = *(const float4*)&g_as[s * 4];
            sh_alpha[t][0] = __expf(lrelu(asv.x + adv.x) - m0) * i0;
            sh_alpha[t][1] = __expf(lrelu(asv.y + adv.y) - m1) * i1;
            sh_alpha[t][2] = __expf(lrelu(asv.z + adv.z) - m2) * i2;
            sh_alpha[t][3] = __expf(lrelu(asv.w + adv.w) - m3) * i3;
        }
        __syncthreads();
        int cnt = min(128, deg - c0);
        for (int jj = 0; jj < cnt; jj++) {
            float al = sh_alpha[jj][h];
            const float4 v = *(const float4*)&g_xp[(size_t)sh_src[jj] * HD + h * 128 + q * 4];
            acc4.x += al * v.x;
            acc4.y += al * v.y;
            acc4.z += al * v.z;
            acc4.w += al * v.w;
        }
        __syncthreads();
    }
    *(float4*)&xatt[h][q * 4] = acc4;
    __syncthreads();

    // head mean + bias + residual + RMSNorm (thread t owns dim t)
    float a = 0.25f * (xatt[0][t] + xatt[1][t] + xatt[2][t] + xatt[3][t]);
    float v = g_x[n * DD + t] + a + bias[t];
    shred[t] = v * v;
    __syncthreads();
#pragma unroll
    for (int o = 64; o; o >>= 1) {
        if (t < o) shred[t] += shred[t + o];
        __syncthreads();
    }
    float r = rsqrtf(shred[0] * (1.0f / DD) + EPS_);
    g_x[n * DD + t] = v * r * nw[t];
}

// ---------------- residual + RMSNorm after FFN ----------------
__global__ __launch_bounds__(128) void k_resnorm(const float* __restrict__ nw) {
    int n = blockIdx.x, t = threadIdx.x;
    __shared__ float shred[128];
    float v = g_x[n * DD + t] + g_tmp[n * DD + t];
    shred[t] = v * v;
    __syncthreads();
#pragma unroll
    for (int o = 64; o; o >>= 1) {
        if (t < o) shred[t] += shred[t + o];
        __syncthreads();
    }
    float r = rsqrtf(shred[0] * (1.0f / DD) + EPS_);
    g_x[n * DD + t] = v * r * nw[t];
}

// ---------------- host ----------------
extern "C" void kernel_launch(void* const* d_in, const int* in_sizes, int n_in,
                              void* d_out, int out_size) {
    const float* x        = (const float*)d_in[0];
    const float* W_gat    = (const float*)d_in[1];
    const float* att_src  = (const float*)d_in[2];
    const float* att_dst  = (const float*)d_in[3];
    const float* bias_gat = (const float*)d_in[4];
    const float* W1       = (const float*)d_in[5];
    const float* b1       = (const float*)d_in[6];
    const float* W2       = (const float*)d_in[7];
    const float* b2       = (const float*)d_in[8];
    const float* n1w      = (const float*)d_in[9];
    const float* n2w      = (const float*)d_in[10];
    const void*  ei       = d_in[11];

    float *xbuf, *xpbuf, *h1buf, *tmpbuf;
    cudaGetSymbolAddress((void**)&xbuf, g_x);
    cudaGetSymbolAddress((void**)&xpbuf, g_xp);
    cudaGetSymbolAddress((void**)&h1buf, g_h1);
    cudaGetSymbolAddress((void**)&tmpbuf, g_tmp);

    // CSR build
    k_detect<<<1, 256>>>((const unsigned*)ei);
    k_initdeg<<<(NV + 255) / 256, 256>>>();
    k_count<<<(EE + 255) / 256, 256>>>(ei);
    k_scan<<<1, 1024>>>();
    k_fill<<<(NV + 255) / 256, 256>>>();
    k_scatter<<<(EE + 255) / 256, 256>>>(ei);

    k_loadx<<<(NV * DD / 4 + 255) / 256, 256>>>((const float4*)x);

    for (int i = 0; i < LL; i++) {
        gemm_tf32<<<dim3(HD / 128, MTILES), 256>>>(
            xbuf, W_gat + (size_t)i * DD * HD, nullptr, xpbuf, HD, 0);
        k_dots<<<(NV + 3) / 4, 128>>>(att_src + i * HD, att_dst + i * HD);
        k_agg<<<NV, 128>>>(bias_gat + i * DD, n1w + i * DD);
        gemm_tf32<<<dim3(1, MTILES), 256>>>(
            xbuf, W1 + (size_t)i * DD * DD, b1 + i * DD, h1buf, DD, 1);
        gemm_tf32<<<dim3(1, MTILES), 256>>>(
            h1buf, W2 + (size_t)i * DD * DD, b2 + i * DD, tmpbuf, DD, 0);
        k_resnorm<<<NV, 128>>>(n2w + i * DD);
    }

    k_storeout<<<(NV * DD / 4 + 255) / 256, 256>>>((float4*)d_out);
}

// round 3
// speedup vs baseline: 1.9270x; 1.5410x over previous
#include <cuda_runtime.h>
#include <cuda_fp16.h>
#include <mma.h>
using namespace nvcuda;

#define NV 20000
#define EE 320000
#define DD 128
#define HD 512
#define LL 3
#define MTILES 157
#define NV2 (MTILES * 128)   /* 20096 padded rows */
#define EPS_ 1.1920929e-07f

// ---------------- static device scratch ----------------
__device__ float  g_x  [NV2 * DD];            // fp32 running features (residual precision)
__device__ __half g_xh [NV2 * DD];            // fp16 mirror (GEMM A operand)
__device__ __half g_xph[(size_t)NV2 * HD];    // fp16 xp = x @ W_gat
__device__ __half g_h1h[NV2 * DD];            // fp16 FFN hidden
__device__ __half g_Wg [LL * DD * HD];        // fp16 weights
__device__ __half g_W1h[LL * DD * DD];
__device__ __half g_W2h[LL * DD * DD];
__device__ float  g_as[NV * 4];
__device__ float  g_ad[NV * 4];
__device__ int    g_rowptr[NV + 1];
__device__ int    g_deg[NV];
__device__ int    g_cursor[NV];
__device__ int    g_col[EE + NV];
__device__ int    g_is64;

__device__ __forceinline__ int edge_at(const void* ei, long long idx) {
    return g_is64 ? (int)((const long long*)ei)[idx] : ((const int*)ei)[idx];
}

// ---------------- fused setup: x copy/convert + weight convert + deg init + dtype detect ----------------
#define WHALF ((LL * DD * HD + 2 * LL * DD * DD) / 2)  /* 147456 half2 ops */

__global__ void k_setup(const float4* __restrict__ x,
                        const float* __restrict__ Wg,
                        const float* __restrict__ W1,
                        const float* __restrict__ W2,
                        const unsigned* __restrict__ ei_w) {
    int i = blockIdx.x * 256 + threadIdx.x;
    if (i < NV * DD / 4) {
        float4 v = x[i];
        ((float4*)g_x)[i] = v;
        ((__half2*)g_xh)[i * 2]     = __floats2half2_rn(v.x, v.y);
        ((__half2*)g_xh)[i * 2 + 1] = __floats2half2_rn(v.z, v.w);
    }
    if (i < WHALF) {
        int j = i * 2;
        const float* src; __half* dst; int off;
        if (j < LL * DD * HD)                    { src = Wg; dst = g_Wg;  off = j; }
        else if (j < LL * DD * HD + LL * DD * DD){ src = W1; dst = g_W1h; off = j - LL * DD * HD; }
        else                                     { src = W2; dst = g_W2h; off = j - LL * DD * HD - LL * DD * DD; }
        float2 v = *(const float2*)(src + off);
        *(__half2*)(dst + off) = __floats2half2_rn(v.x, v.y);
    }
    if (i < NV) g_deg[i] = 1;  // self loop
    if (blockIdx.x == 0) {
        __shared__ unsigned acc;
        if (threadIdx.x == 0) acc = 0u;
        __syncthreads();
        unsigned v = 0;
        for (int k = threadIdx.x; k < 2048; k += 256) v |= ei_w[2 * k + 1];
        if (v) atomicOr(&acc, 1u);
        __syncthreads();
        if (threadIdx.x == 0) g_is64 = (acc == 0u) ? 1 : 0;
    }
}

// ---------------- CSR build ----------------
__global__ void k_count(const void* ei) {
    int e = blockIdx.x * 256 + threadIdx.x;
    if (e < EE) atomicAdd(&g_deg[edge_at(ei, (long long)EE + e)], 1);
}
__global__ __launch_bounds__(1024) void k_scan() {
    const int PER = 20;  // NV/1000; threads 0..999 fully in range
    __shared__ int wsum[32];
    int t = threadIdx.x, lane = t & 31, w = t >> 5;
    int v[PER];
    int base = t * PER;
    int run = 0;
    if (base < NV) {
        const int4* p = (const int4*)(g_deg + base);
#pragma unroll
        for (int q = 0; q < 5; q++) {
            int4 d = p[q];
            run += d.x; v[q * 4 + 0] = run;
            run += d.y; v[q * 4 + 1] = run;
            run += d.z; v[q * 4 + 2] = run;
            run += d.w; v[q * 4 + 3] = run;
        }
    } else {
#pragma unroll
        for (int q = 0; q < PER; q++) v[q] = 0;
    }
    int tot = run, sc = tot;
#pragma unroll
    for (int o = 1; o < 32; o <<= 1) {
        int u = __shfl_up_sync(0xffffffffu, sc, o);
        if (lane >= o) sc += u;
    }
    if (lane == 31) wsum[w] = sc;
    __syncthreads();
    if (w == 0) {
        int s = wsum[lane];
#pragma unroll
        for (int o = 1; o < 32; o <<= 1) {
            int u = __shfl_up_sync(0xffffffffu, s, o);
            if (lane >= o) s += u;
        }
        wsum[lane] = s;
    }
    __syncthreads();
    int throff = ((w > 0) ? wsum[w - 1] : 0) + sc - tot;
    if (t == 0) g_rowptr[0] = 0;
    if (base < NV) {
#pragma unroll
        for (int q = 0; q < PER; q++) g_rowptr[base + q + 1] = throff + v[q];
    }
}
__global__ void k_fill() {
    int n = blockIdx.x * 256 + threadIdx.x;
    if (n < NV) {
        int r = g_rowptr[n];
        g_col[r] = n;
        g_cursor[n] = r + 1;
    }
}
__global__ void k_scatter(const void* ei) {
    int e = blockIdx.x * 256 + threadIdx.x;
    if (e < EE) {
        int s = edge_at(ei, e);
        int d = edge_at(ei, (long long)EE + e);
        g_col[atomicAdd(&g_cursor[d], 1)] = s;
    }
}

__global__ void k_storeout(float4* __restrict__ out) {
    int i = blockIdx.x * 256 + threadIdx.x;
    if (i < NV * DD / 4) out[i] = ((const float4*)g_x)[i];
}

// ---------------- fp16 tensor-core GEMM, full-K smem resident ----------------
// C[128-tile rows, Ncols] = A[.,128] x B[128,Ncols] (+bias)
// mode 0: write fp16 Ch              (xp)
// mode 1: relu, write fp16 Ch        (FFN hidden)
// mode 2: fused residual+RMSNorm: v = g_x + C; write g_x fp32 + g_xh fp16 (Ncols==128 only)
// Dynamic smem layout: As half[128][136] | Bs half[128][136] | Brep float[16][136]; staging reuses front.
#define GSMEM 78336

__global__ __launch_bounds__(256) void gemm_h(
    const __half* __restrict__ A, const __half* __restrict__ B,
    const float* __restrict__ bias, __half* __restrict__ Ch,
    const float* __restrict__ nw, int Ncols, int mode)
{
    extern __shared__ char dsm[];
    __half* As = (__half*)dsm;
    __half* Bs = As + 128 * 136;
    float*  Brep = (float*)(dsm + 2 * 128 * 136 * 2);
    float*  stage = (float*)dsm;

    int bm = blockIdx.y * 128, bn = blockIdx.x * 128;
    int t = threadIdx.x, warp = t >> 5, lane = t & 31;
    int wr = warp & 1, wc = warp >> 1;

    for (int i = t; i < 16 * 128; i += 256) {
        int r = i >> 7, c = i & 127;
        Brep[r * 136 + c] = bias ? bias[bn + c] : 0.f;
    }
    __syncthreads();

    wmma::fragment<wmma::accumulator, 16, 16, 16, float> acc[4][2];
#pragma unroll
    for (int fr = 0; fr < 4; fr++)
#pragma unroll
        for (int fc = 0; fc < 2; fc++)
            wmma::load_matrix_sync(acc[fr][fc], &Brep[wc * 32 + fc * 16], 136,
                                   wmma::mem_row_major);

#pragma unroll
    for (int i = 0; i < 8; i++) {
        int idx = t + i * 256;
        int r = idx >> 4, c8 = (idx & 15) * 8;
        *(uint4*)(As + r * 136 + c8) = *(const uint4*)(A + (size_t)(bm + r) * 128 + c8);
        *(uint4*)(Bs + r * 136 + c8) = *(const uint4*)(B + (size_t)r * Ncols + bn + c8);
    }
    __syncthreads();

#pragma unroll
    for (int k = 0; k < 8; k++) {
        wmma::fragment<wmma::matrix_a, 16, 16, 16, __half, wmma::row_major> af[4];
        wmma::fragment<wmma::matrix_b, 16, 16, 16, __half, wmma::row_major> bf[2];
#pragma unroll
        for (int fr = 0; fr < 4; fr++)
            wmma::load_matrix_sync(af[fr], &As[(wr * 64 + fr * 16) * 136 + k * 16], 136);
#pragma unroll
        for (int fc = 0; fc < 2; fc++)
            wmma::load_matrix_sync(bf[fc], &Bs[(k * 16) * 136 + wc * 32 + fc * 16], 136);
#pragma unroll
        for (int fr = 0; fr < 4; fr++)
#pragma unroll
            for (int fc = 0; fc < 2; fc++)
                wmma::mma_sync(acc[fr][fc], af[fr], bf[fc], acc[fr][fc]);
    }
    __syncthreads();  // smem tiles consumed; staging may overwrite

    if (mode == 2) {
        // full 128x128 tile staged (ldm 132), then per-row residual + RMSNorm
#pragma unroll
        for (int fr = 0; fr < 4; fr++)
#pragma unroll
            for (int fc = 0; fc < 2; fc++)
                wmma::store_matrix_sync(&stage[(wr * 64 + fr * 16) * 132 + wc * 32 + fc * 16],
                                        acc[fr][fc], 132, wmma::mem_row_major);
        __syncthreads();
        float4 nwv = *(const float4*)&nw[lane * 4];
        for (int r = warp; r < 128; r += 8) {
            size_t row = (size_t)(bm + r);
            float4 xr = *(const float4*)&g_x[row * 128 + lane * 4];
            float4 st = *(const float4*)&stage[r * 132 + lane * 4];
            float v0 = xr.x + st.x, v1 = xr.y + st.y, v2 = xr.z + st.z, v3 = xr.w + st.w;
            float ss = v0 * v0 + v1 * v1 + v2 * v2 + v3 * v3;
#pragma unroll
            for (int o = 16; o; o >>= 1) ss += __shfl_xor_sync(0xffffffffu, ss, o);
            float rr = rsqrtf(ss * (1.0f / DD) + EPS_);
            float o0 = v0 * rr * nwv.x, o1 = v1 * rr * nwv.y;
            float o2 = v2 * rr * nwv.z, o3 = v3 * rr * nwv.w;
            *(float4*)&g_x[row * 128 + lane * 4] = make_float4(o0, o1, o2, o3);
            __half2 h0 = __floats2half2_rn(o0, o1);
            __half2 h1 = __floats2half2_rn(o2, o3);
            uint2 packed;
            packed.x = *(unsigned*)&h0;
            packed.y = *(unsigned*)&h1;
            *(uint2*)&g_xh[row * 128 + lane * 4] = packed;
        }
    } else {
        if (mode == 1) {
#pragma unroll
            for (int fr = 0; fr < 4; fr++)
#pragma unroll
                for (int fc = 0; fc < 2; fc++)
#pragma unroll
                    for (int i = 0; i < acc[fr][fc].num_elements; i++)
                        acc[fr][fc].x[i] = fmaxf(acc[fr][fc].x[i], 0.f);
        }
        float* ws = stage + warp * 64 * 36;
#pragma unroll
        for (int fr = 0; fr < 4; fr++)
#pragma unroll
            for (int fc = 0; fc < 2; fc++)
                wmma::store_matrix_sync(&ws[fr * 16 * 36 + fc * 16], acc[fr][fc], 36,
                                        wmma::mem_row_major);
        __syncwarp();
        for (int i = lane; i < 64 * 32; i += 32) {
            int r = i >> 5, c = i & 31;
            Ch[(size_t)(bm + wr * 64 + r) * Ncols + bn + wc * 32 + c] =
                __float2half(ws[r * 36 + c]);
        }
    }
}

// ---------------- attention dots (fp16 xp) ----------------
__global__ __launch_bounds__(128) void k_dots(const float* __restrict__ att_s,
                                              const float* __restrict__ att_d) {
    int warp = threadIdx.x >> 5, lane = threadIdx.x & 31;
    int n = blockIdx.x * 4 + warp;
    if (n >= NV) return;
    const __half* xpr = g_xph + (size_t)n * HD;
#pragma unroll
    for (int h = 0; h < 4; h++) {
        uint2 raw = *(const uint2*)(xpr + h * 128 + lane * 4);
        float2 f0 = __half22float2(*(__half2*)&raw.x);
        float2 f1 = __half22float2(*(__half2*)&raw.y);
        float4 as = *(const float4*)&att_s[h * 128 + lane * 4];
        float4 ad = *(const float4*)&att_d[h * 128 + lane * 4];
        float ps = f0.x * as.x + f0.y * as.y + f1.x * as.z + f1.y * as.w;
        float pd = f0.x * ad.x + f0.y * ad.y + f1.x * ad.z + f1.y * ad.w;
#pragma unroll
        for (int o = 16; o; o >>= 1) {
            ps += __shfl_xor_sync(0xffffffffu, ps, o);
            pd += __shfl_xor_sync(0xffffffffu, pd, o);
        }
        if (lane == 0) {
            g_as[n * 4 + h] = ps;
            g_ad[n * 4 + h] = pd;
        }
    }
}

__device__ __forceinline__ float lrelu(float x) { return x > 0.f ? x : 0.2f * x; }

__device__ __forceinline__ void comb(float& m, float& s, float m2, float s2) {
    float M = fmaxf(m, m2);
    s = s * __expf(m - M) + s2 * __expf(m2 - M);
    m = M;
}

// ---------------- fused GAT aggregation: online softmax + fp16 gather + head mean
//                  + bias + residual + RMSNorm. 128 threads / dst node.
__global__ __launch_bounds__(128) void k_agg(const float* __restrict__ bias,
                                             const float* __restrict__ nw) {
    int n = blockIdx.x, t = threadIdx.x;
    int start = g_rowptr[n];
    int deg = g_rowptr[n + 1] - start;

    __shared__ float smm[4][4], sms[4][4];
    __shared__ float sh_alpha[128][4];
    __shared__ int sh_src[128];
    __shared__ float xatt[4][128];
    __shared__ float shred[128];

    float4 adv = *(const float4*)&g_ad[n * 4];

    // single online pass: per-head (max, sum)
    float m[4] = {-1e30f, -1e30f, -1e30f, -1e30f};
    float s[4] = {0.f, 0.f, 0.f, 0.f};
    for (int j = t; j < deg; j += 128) {
        int src = g_col[start + j];
        float4 asv = *(const float4*)&g_as[src * 4];
        float e[4] = {lrelu(asv.x + adv.x), lrelu(asv.y + adv.y),
                      lrelu(asv.z + adv.z), lrelu(asv.w + adv.w)};
#pragma unroll
        for (int h = 0; h < 4; h++) comb(m[h], s[h], e[h], 1.f);
    }
    int lane = t & 31, w = t >> 5;
#pragma unroll
    for (int h = 0; h < 4; h++) {
#pragma unroll
        for (int o = 16; o; o >>= 1) {
            float m2 = __shfl_xor_sync(0xffffffffu, m[h], o);
            float s2 = __shfl_xor_sync(0xffffffffu, s[h], o);
            comb(m[h], s[h], m2, s2);
        }
        if (lane == 0) { smm[w][h] = m[h]; sms[w][h] = s[h]; }
    }
    __syncthreads();
    float M[4], inv[4];
#pragma unroll
    for (int h = 0; h < 4; h++) {
        float Mx = fmaxf(fmaxf(smm[0][h], smm[1][h]), fmaxf(smm[2][h], smm[3][h]));
        float S = sms[0][h] * __expf(smm[0][h] - Mx) + sms[1][h] * __expf(smm[1][h] - Mx)
                + sms[2][h] * __expf(smm[2][h] - Mx) + sms[3][h] * __expf(smm[3][h] - Mx);
        M[h] = Mx;
        inv[h] = 1.f / S;
    }

    // gather pass: thread owns (head h, quad q) -> 4 dims (fp16 loads)
    int h = t >> 5, q = t & 31;
    float4 acc4 = make_float4(0.f, 0.f, 0.f, 0.f);
    for (int c0 = 0; c0 < deg; c0 += 128) {
        int j = c0 + t;
        if (j < deg) {
            int src = g_col[start + j];
            sh_src[t] = src;
            float4 asv = *(const float4*)&g_as[src * 4];
            sh_alpha[t][0] = __expf(lrelu(asv.x + adv.x) - M[0]) * inv[0];
            sh_alpha[t][1] = __expf(lrelu(asv.y + adv.y) - M[1]) * inv[1];
            sh_alpha[t][2] = __expf(lrelu(asv.z + adv.z) - M[2]) * inv[2];
            sh_alpha[t][3] = __expf(lrelu(asv.w + adv.w) - M[3]) * inv[3];
        }
        __syncthreads();
        int cnt = min(128, deg - c0);
        for (int jj = 0; jj < cnt; jj++) {
            float al = sh_alpha[jj][h];
            uint2 raw = *(const uint2*)(g_xph + (size_t)sh_src[jj] * HD + h * 128 + q * 4);
            float2 f0 = __half22float2(*(__half2*)&raw.x);
            float2 f1 = __half22float2(*(__half2*)&raw.y);
            acc4.x += al * f0.x;
            acc4.y += al * f0.y;
            acc4.z += al * f1.x;
            acc4.w += al * f1.y;
        }
        __syncthreads();
    }
    *(float4*)&xatt[h][q * 4] = acc4;
    __syncthreads();

    float a = 0.25f * (xatt[0][t] + xatt[1][t] + xatt[2][t] + xatt[3][t]);
    float v = g_x[n * DD + t] + a + bias[t];
    shred[t] = v * v;
    __syncthreads();
#pragma unroll
    for (int o = 64; o; o >>= 1) {
        if (t < o) shred[t] += shred[t + o];
        __syncthreads();
    }
    float r = rsqrtf(shred[0] * (1.0f / DD) + EPS_);
    float o = v * r * nw[t];
    g_x[n * DD + t] = o;
    g_xh[n * DD + t] = __float2half(o);
}

// ---------------- host ----------------
extern "C" void kernel_launch(void* const* d_in, const int* in_sizes, int n_in,
                              void* d_out, int out_size) {
    const float* x        = (const float*)d_in[0];
    const float* W_gat    = (const float*)d_in[1];
    const float* att_src  = (const float*)d_in[2];
    const float* att_dst  = (const float*)d_in[3];
    const float* bias_gat = (const float*)d_in[4];
    const float* W1       = (const float*)d_in[5];
    const float* b1       = (const float*)d_in[6];
    const float* W2       = (const float*)d_in[7];
    const float* b2       = (const float*)d_in[8];
    const float* n1w      = (const float*)d_in[9];
    const float* n2w      = (const float*)d_in[10];
    const void*  ei       = d_in[11];

    static int smem_set = 0;
    if (!smem_set) {
        cudaFuncSetAttribute(gemm_h, cudaFuncAttributeMaxDynamicSharedMemorySize, GSMEM);
        smem_set = 1;
    }

    __half *xh, *xph, *h1h, *Wg, *W1h, *W2h;
    cudaGetSymbolAddress((void**)&xh,  g_xh);
    cudaGetSymbolAddress((void**)&xph, g_xph);
    cudaGetSymbolAddress((void**)&h1h, g_h1h);
    cudaGetSymbolAddress((void**)&Wg,  g_Wg);
    cudaGetSymbolAddress((void**)&W1h, g_W1h);
    cudaGetSymbolAddress((void**)&W2h, g_W2h);

    k_setup<<<2500, 256>>>((const float4*)x, W_gat, W1, W2, (const unsigned*)ei);
    k_count<<<(EE + 255) / 256, 256>>>(ei);
    k_scan<<<1, 1024>>>();
    k_fill<<<(NV + 255) / 256, 256>>>();
    k_scatter<<<(EE + 255) / 256, 256>>>(ei);

    for (int i = 0; i < LL; i++) {
        gemm_h<<<dim3(HD / 128, MTILES), 256, GSMEM>>>(
            xh, Wg + (size_t)i * DD * HD, nullptr, xph, nullptr, HD, 0);
        k_dots<<<(NV + 3) / 4, 128>>>(att_src + i * HD, att_dst + i * HD);
        k_agg<<<NV, 128>>>(bias_gat + i * DD, n1w + i * DD);
        gemm_h<<<dim3(1, MTILES), 256, GSMEM>>>(
            xh, W1h + (size_t)i * DD * DD, b1 + i * DD, h1h, nullptr, DD, 1);
        gemm_h<<<dim3(1, MTILES), 256, GSMEM>>>(
            h1h, W2h + (size_t)i * DD * DD, b2 + i * DD, nullptr, n2w + i * DD, DD, 2);
    }

    k_storeout<<<(NV * DD / 4 + 255) / 256, 256>>>((float4*)d_out);
}